// round 10
// baseline (speedup 1.0000x reference)
#include <cuda_runtime.h>
#include <cuda_fp16.h>
#include <cstdint>

// ============================================================================
// Problem constants (fixed shapes for SVMModel_19267223290147)
// ============================================================================
#define BB 2048      // batch rows
#define NN 32768     // train rows
#define DD 128       // feature dim
#define BT 128       // CTA B-tile (M)
#define NT 128       // CTA N-tile
#define NSPLITS 16   // N chunks across grid.x
#define BTILES  16   // B tiles across grid.y
#define NCHUNK (NN / NSPLITS)     // 2048
#define TILES  (NCHUNK / NT)      // 16
#define THREADS 256

// SMEM layout: A tile + double-buffered B tiles (96KB -> 2 CTAs/SM fit 228KB).
#define SMEM_A  0
#define SMEM_B0 32768
#define SMEM_B1 65536
#define SMEM_TOTAL 98304

#define SWZ(o) ((o) ^ (((o) >> 3) & 0x70))

// ============================================================================
// Device globals (static allocation: allowed)
// ============================================================================
__device__ __half g_xbf[BB * DD];              // x * (2*gamma*log2e) fp16
__device__ __half g_tbf[NN * DD];              // train_data fp16
__device__ float  g_c1[NN];                    // W[n] * exp(-g*t2[n])
__device__ float  g_ex[BB];                    // exp(-g*x2[b])
__device__ float  g_partial[NSPLITS * BB];

// ============================================================================
// PTX helpers (sm_100 base-target safe)
// ============================================================================
__device__ __forceinline__ uint32_t smem_u32(const void* p) {
    uint32_t a;
    asm("{ .reg .u64 t; cvta.to.shared.u64 t, %1; cvt.u32.u64 %0, t; }" : "=r"(a) : "l"(p));
    return a;
}
__device__ __forceinline__ float ex2f(float x) {
    float y; asm("ex2.approx.f32 %0, %1;" : "=f"(y) : "f"(x)); return y;
}
__device__ __forceinline__ void cp_async16(uint32_t dst, const void* src) {
    asm volatile("cp.async.cg.shared.global [%0], [%1], 16;" :: "r"(dst), "l"(src));
}
#define CP_COMMIT() asm volatile("cp.async.commit_group;" ::: "memory")

__device__ __forceinline__ void ldsm4(uint32_t* r, uint32_t addr) {
    asm volatile("ldmatrix.sync.aligned.m8n8.x4.shared.b16 {%0,%1,%2,%3}, [%4];"
                 : "=r"(r[0]), "=r"(r[1]), "=r"(r[2]), "=r"(r[3]) : "r"(addr));
}
__device__ __forceinline__ void mma16816(float* c, const uint32_t* a, const uint32_t* b) {
    asm volatile(
        "mma.sync.aligned.m16n8k16.row.col.f32.f16.f16.f32 "
        "{%0,%1,%2,%3}, {%4,%5,%6,%7}, {%8,%9}, {%0,%1,%2,%3};"
        : "+f"(c[0]), "+f"(c[1]), "+f"(c[2]), "+f"(c[3])
        : "r"(a[0]), "r"(a[1]), "r"(a[2]), "r"(a[3]), "r"(b[0]), "r"(b[1]));
}

// cp.async one [128 x 128 fp16] tile into SMEM (chunked SW128 layout).
__device__ __forceinline__ void issue_tile(uint32_t sm_base, const __half* src) {
    int tid = threadIdx.x;
    #pragma unroll
    for (int it = 0; it < 8; it++) {
        int k = tid + it * 256;
        int row = k >> 4;
        int rem = k & 15;
        int c = rem >> 3;
        int j = rem & 7;
        uint32_t dst = sm_base + c * 16384 + SWZ((uint32_t)(row * 128 + j * 16));
        cp_async16(dst, src + row * 128 + c * 64 + j * 8);
    }
}

// ============================================================================
// Prep kernels (fp32 norms; x pre-scaled by 2*gamma*log2e)
// ============================================================================
__global__ void prep_x_kernel(const float* __restrict__ x, const float* __restrict__ gamma) {
    int w = (blockIdx.x * blockDim.x + threadIdx.x) >> 5;
    int lane = threadIdx.x & 31;
    if (w >= BB) return;
    float gm = gamma[0];
    float s = 2.0f * gm * 1.4426950408889634f;
    float4 v = reinterpret_cast<const float4*>(x + w * DD)[lane];
    float ss = v.x * v.x + v.y * v.y + v.z * v.z + v.w * v.w;
    #pragma unroll
    for (int o = 16; o > 0; o >>= 1) ss += __shfl_xor_sync(0xFFFFFFFFu, ss, o);
    __half2* dst = reinterpret_cast<__half2*>(g_xbf + w * DD + lane * 4);
    dst[0] = __floats2half2_rn(v.x * s, v.y * s);
    dst[1] = __floats2half2_rn(v.z * s, v.w * s);
    if (lane == 0) g_ex[w] = expf(-gm * ss);
}

__global__ void prep_t_kernel(const float* __restrict__ t, const float* __restrict__ gamma,
                              const float* __restrict__ W) {
    int w = (blockIdx.x * blockDim.x + threadIdx.x) >> 5;
    int lane = threadIdx.x & 31;
    if (w >= NN) return;
    float4 v = reinterpret_cast<const float4*>(t + w * DD)[lane];
    float ss = v.x * v.x + v.y * v.y + v.z * v.z + v.w * v.w;
    #pragma unroll
    for (int o = 16; o > 0; o >>= 1) ss += __shfl_xor_sync(0xFFFFFFFFu, ss, o);
    __half2* dst = reinterpret_cast<__half2*>(g_tbf + w * DD + lane * 4);
    dst[0] = __floats2half2_rn(v.x, v.y);
    dst[1] = __floats2half2_rn(v.z, v.w);
    if (lane == 0) g_c1[w] = W[w] * expf(-gamma[0] * ss);
}

// ============================================================================
// Main kernel: 2 CTAs/SM (reg cap 128). 8 warps x [16 rows, 128 cols].
// A-hoist = 32 regs; B in nb-pairs (dep distance 2); per-pair exp2 epilogue.
// ============================================================================
__global__ void __launch_bounds__(THREADS, 2)
rbf_main_kernel() {
    extern __shared__ char smem[];
    uint32_t sb = smem_u32(smem);
    int tid = threadIdx.x;
    int lane = tid & 31;
    int wid = tid >> 5;       // 8 warps along M (16 rows each)
    int g  = lane >> 2;
    int tg = lane & 3;

    int ns = blockIdx.x;
    int bt = blockIdx.y;
    int m0 = bt * BT;
    int n_base = ns * NCHUNK;

    // Prologue: A tile + B0 (group 0), B1 (group 1)
    issue_tile(sb + SMEM_A, g_xbf + (size_t)m0 * DD);
    issue_tile(sb + SMEM_B0, g_tbf + (size_t)n_base * DD);
    CP_COMMIT();
    issue_tile(sb + SMEM_B1, g_tbf + (size_t)(n_base + NT) * DD);
    CP_COMMIT();

    int a_row_in_warp = ((lane >> 3) & 1) * 8 + (lane & 7);
    int a_kb16 = ((lane >> 4) & 1) * 16;
    int b_row_in_nb = lane & 7;
    int b_kb16 = (lane >> 3) * 16;

    asm volatile("cp.async.wait_group 1;" ::: "memory");  // A + B0 resident
    __syncthreads();

    // Hoist A fragments: this warp's 16 rows, all K -> 32 regs.
    uint32_t af[4][2][4];   // [kq][kk][4]
    {
        int row = wid * 16 + a_row_in_warp;
        #pragma unroll
        for (int kq = 0; kq < 4; kq++) {
            int chunk = kq >> 1;
            int kbyte0 = (kq & 1) * 64;
            uint32_t base = sb + SMEM_A + chunk * 16384;
            ldsm4(af[kq][0], base + SWZ((uint32_t)(row * 128 + kbyte0 + a_kb16)));
            ldsm4(af[kq][1], base + SWZ((uint32_t)(row * 128 + kbyte0 + 32 + a_kb16)));
        }
    }

    float racc[2] = {0.f, 0.f};   // [h]: rows g, g+8

    for (int i = 0; i < TILES; i++) {
        if (i + 1 < TILES) { asm volatile("cp.async.wait_group 1;" ::: "memory"); }
        else               { asm volatile("cp.async.wait_group 0;" ::: "memory"); }
        __syncthreads();

        uint32_t Bb = sb + ((i & 1) ? SMEM_B1 : SMEM_B0);
        const float* c1base = g_c1 + n_base + i * NT;

        // 8 pairs of nb (16 nb = 128 cols). Per pair: 8 ldsm, 16 MMA
        // (2 indep chains, dep distance 2), then the exp2 epilogue.
        #pragma unroll
        for (int np = 0; np < 8; np++) {
            uint32_t bf[2][4][4];   // [nb2][kq][k-sub]
            #pragma unroll
            for (int nb2 = 0; nb2 < 2; nb2++) {
                int row = (np * 2 + nb2) * 8 + b_row_in_nb;
                #pragma unroll
                for (int kq = 0; kq < 4; kq++) {
                    int chunk = kq >> 1;
                    int kbyte0 = (kq & 1) * 64;
                    ldsm4(bf[nb2][kq], Bb + chunk * 16384 +
                          SWZ((uint32_t)(row * 128 + kbyte0 + b_kb16)));
                }
            }
            float acc[2][4] = {{0.f,0.f,0.f,0.f},{0.f,0.f,0.f,0.f}};
            #pragma unroll
            for (int kq = 0; kq < 4; kq++)
                #pragma unroll
                for (int kk = 0; kk < 2; kk++)
                    #pragma unroll
                    for (int nb2 = 0; nb2 < 2; nb2++)
                        mma16816(acc[nb2], af[kq][kk], &bf[nb2][kq][kk * 2]);

            #pragma unroll
            for (int nb2 = 0; nb2 < 2; nb2++) {
                float2 w = *reinterpret_cast<const float2*>(
                    c1base + (np * 2 + nb2) * 8 + 2 * tg);
                racc[0] = fmaf(ex2f(acc[nb2][0]), w.x, racc[0]);
                racc[0] = fmaf(ex2f(acc[nb2][1]), w.y, racc[0]);
                racc[1] = fmaf(ex2f(acc[nb2][2]), w.x, racc[1]);
                racc[1] = fmaf(ex2f(acc[nb2][3]), w.y, racc[1]);
            }
        }

        __syncthreads();   // all warps done reading Bb
        if (i + 2 < TILES) {
            issue_tile(Bb, g_tbf + (size_t)(n_base + (i + 2) * NT) * DD);
            CP_COMMIT();
        }
    }

    // Reduce over the 4 lanes sharing each row; deterministic partial write.
    #pragma unroll
    for (int h = 0; h < 2; h++) {
        float v = racc[h];
        v += __shfl_xor_sync(0xFFFFFFFFu, v, 1);
        v += __shfl_xor_sync(0xFFFFFFFFu, v, 2);
        if (tg == 0) {
            int b = m0 + wid * 16 + h * 8 + g;
            g_partial[ns * BB + b] = v;
        }
    }
}

// ============================================================================
// Final reduction: out[b] = e_x[b] * sum(partials) + bias
// ============================================================================
__global__ void reduce_kernel(const float* __restrict__ bias, float* __restrict__ out) {
    int b = blockIdx.x * blockDim.x + threadIdx.x;
    if (b >= BB) return;
    float s = 0.0f;
    #pragma unroll
    for (int ns = 0; ns < NSPLITS; ns++) s += g_partial[ns * BB + b];
    out[b] = fmaf(g_ex[b], s, __ldg(bias));
}

// ============================================================================
// Entry
// ============================================================================
extern "C" void kernel_launch(void* const* d_in, const int* in_sizes, int n_in,
                              void* d_out, int out_size) {
    const float* x     = (const float*)d_in[0];   // [2048, 128]
    const float* train = (const float*)d_in[1];   // [32768, 128]
    const float* gamma = (const float*)d_in[2];   // [1]
    const float* W     = (const float*)d_in[3];   // [1, 32768]
    const float* bias  = (const float*)d_in[4];   // [1]
    float* out = (float*)d_out;                   // [2048, 1]

    cudaFuncSetAttribute(rbf_main_kernel,
                         cudaFuncAttributeMaxDynamicSharedMemorySize, SMEM_TOTAL);

    prep_x_kernel<<<(BB * 32) / THREADS, THREADS>>>(x, gamma);
    prep_t_kernel<<<(NN * 32) / THREADS, THREADS>>>(train, gamma, W);
    rbf_main_kernel<<<dim3(NSPLITS, BTILES), THREADS, SMEM_TOTAL>>>();
    reduce_kernel<<<BB / THREADS, THREADS>>>(bias, out);
}

// round 11
// speedup vs baseline: 1.0294x; 1.0294x over previous
#include <cuda_runtime.h>
#include <cuda_fp16.h>
#include <cstdint>

// ============================================================================
// Problem constants (fixed shapes for SVMModel_19267223290147)
// ============================================================================
#define BB 2048      // batch rows
#define NN 32768     // train rows
#define DD 128       // feature dim
#define BT 128       // CTA B-tile (M)
#define NT 128       // CTA N-tile
#define NSPLITS 8    // N chunks across grid.x
#define BTILES  16   // B tiles across grid.y
#define NCHUNK (NN / NSPLITS)     // 4096
#define TILES  (NCHUNK / NT)      // 32
#define THREADS 256

// SMEM layout: A tile + double-buffered B tiles + double-buffered c1 slices.
#define SMEM_A   0
#define SMEM_B0  32768
#define SMEM_B1  65536
#define SMEM_C10 98304
#define SMEM_C11 98816
#define SMEM_TOTAL 99328

#define SWZ(o) ((o) ^ (((o) >> 3) & 0x70))

// ============================================================================
// Device globals (static allocation: allowed)
// ============================================================================
__device__ __half g_xbf[BB * DD];              // x * (2*gamma*log2e) fp16
__device__ __half g_tbf[NN * DD];              // train_data fp16
__device__ float  g_c1[NN];                    // W[n] * exp(-g*t2[n])
__device__ float  g_ex[BB];                    // exp(-g*x2[b])
__device__ float  g_partial[NSPLITS * BB * 2];

// ============================================================================
// PTX helpers (sm_100 base-target safe)
// ============================================================================
__device__ __forceinline__ uint32_t smem_u32(const void* p) {
    uint32_t a;
    asm("{ .reg .u64 t; cvta.to.shared.u64 t, %1; cvt.u32.u64 %0, t; }" : "=r"(a) : "l"(p));
    return a;
}
__device__ __forceinline__ float ex2f(float x) {
    float y; asm("ex2.approx.f32 %0, %1;" : "=f"(y) : "f"(x)); return y;
}
__device__ __forceinline__ float2 lds64f(uint32_t addr) {
    float2 v;
    asm volatile("ld.shared.v2.f32 {%0, %1}, [%2];" : "=f"(v.x), "=f"(v.y) : "r"(addr));
    return v;
}
__device__ __forceinline__ void cp_async16(uint32_t dst, const void* src) {
    asm volatile("cp.async.cg.shared.global [%0], [%1], 16;" :: "r"(dst), "l"(src));
}
#define CP_COMMIT() asm volatile("cp.async.commit_group;" ::: "memory")

__device__ __forceinline__ void ldsm4(uint32_t* r, uint32_t addr) {
    asm volatile("ldmatrix.sync.aligned.m8n8.x4.shared.b16 {%0,%1,%2,%3}, [%4];"
                 : "=r"(r[0]), "=r"(r[1]), "=r"(r[2]), "=r"(r[3]) : "r"(addr));
}
__device__ __forceinline__ void mma16816(float* c, const uint32_t* a, const uint32_t* b) {
    asm volatile(
        "mma.sync.aligned.m16n8k16.row.col.f32.f16.f16.f32 "
        "{%0,%1,%2,%3}, {%4,%5,%6,%7}, {%8,%9}, {%0,%1,%2,%3};"
        : "+f"(c[0]), "+f"(c[1]), "+f"(c[2]), "+f"(c[3])
        : "r"(a[0]), "r"(a[1]), "r"(a[2]), "r"(a[3]), "r"(b[0]), "r"(b[1]));
}

// cp.async one [128 x 128 fp16] tile into SMEM (chunked SW128 layout).
__device__ __forceinline__ void issue_tile(uint32_t sm_base, const __half* src) {
    int tid = threadIdx.x;
    #pragma unroll
    for (int it = 0; it < 8; it++) {
        int k = tid + it * 256;
        int row = k >> 4;
        int rem = k & 15;
        int c = rem >> 3;
        int j = rem & 7;
        uint32_t dst = sm_base + c * 16384 + SWZ((uint32_t)(row * 128 + j * 16));
        cp_async16(dst, src + row * 128 + c * 64 + j * 8);
    }
}

// cp.async the 512B c1 slice for one tile (threads 0..31, 16B each).
__device__ __forceinline__ void issue_c1(uint32_t sm_c1, const float* src) {
    int tid = threadIdx.x;
    if (tid < 32) cp_async16(sm_c1 + tid * 16, src + tid * 4);
}

// ============================================================================
// Prep kernels (fp32 norms; x pre-scaled by 2*gamma*log2e)
// ============================================================================
__global__ void prep_x_kernel(const float* __restrict__ x, const float* __restrict__ gamma) {
    int w = (blockIdx.x * blockDim.x + threadIdx.x) >> 5;
    int lane = threadIdx.x & 31;
    if (w >= BB) return;
    float gm = gamma[0];
    float s = 2.0f * gm * 1.4426950408889634f;
    float4 v = reinterpret_cast<const float4*>(x + w * DD)[lane];
    float ss = v.x * v.x + v.y * v.y + v.z * v.z + v.w * v.w;
    #pragma unroll
    for (int o = 16; o > 0; o >>= 1) ss += __shfl_xor_sync(0xFFFFFFFFu, ss, o);
    __half2* dst = reinterpret_cast<__half2*>(g_xbf + w * DD + lane * 4);
    dst[0] = __floats2half2_rn(v.x * s, v.y * s);
    dst[1] = __floats2half2_rn(v.z * s, v.w * s);
    if (lane == 0) g_ex[w] = expf(-gm * ss);
}

__global__ void prep_t_kernel(const float* __restrict__ t, const float* __restrict__ gamma,
                              const float* __restrict__ W) {
    int w = (blockIdx.x * blockDim.x + threadIdx.x) >> 5;
    int lane = threadIdx.x & 31;
    if (w >= NN) return;
    float4 v = reinterpret_cast<const float4*>(t + w * DD)[lane];
    float ss = v.x * v.x + v.y * v.y + v.z * v.z + v.w * v.w;
    #pragma unroll
    for (int o = 16; o > 0; o >>= 1) ss += __shfl_xor_sync(0xFFFFFFFFu, ss, o);
    __half2* dst = reinterpret_cast<__half2*>(g_tbf + w * DD + lane * 4);
    dst[0] = __floats2half2_rn(v.x, v.y);
    dst[1] = __floats2half2_rn(v.z, v.w);
    if (lane == 0) g_c1[w] = W[w] * expf(-gamma[0] * ss);
}

// ============================================================================
// Main kernel: R9 structure (nb pairs, 4 indep chains); ONLY change =
// c1 staged through SMEM via the cp.async pipeline (LDS 29cyc vs LDG 234cyc).
// ============================================================================
__global__ void __launch_bounds__(THREADS, 1)
rbf_main_kernel() {
    extern __shared__ char smem[];
    uint32_t sb = smem_u32(smem);
    int tid = threadIdx.x;
    int lane = tid & 31;
    int wid = tid >> 5;
    int warp_m = wid & 3;     // 4 warps along M (32 rows each)
    int warp_n = wid >> 2;    // 2 warps along N (64 cols each)
    int g  = lane >> 2;
    int tg = lane & 3;

    int m0 = blockIdx.y * BT;
    int ns = blockIdx.x;
    int n_base = ns * NCHUNK;

    // Prologue: A tile + (B0,c1_0) group 0, (B1,c1_1) group 1
    issue_tile(sb + SMEM_A, g_xbf + (size_t)m0 * DD);
    issue_tile(sb + SMEM_B0, g_tbf + (size_t)n_base * DD);
    issue_c1(sb + SMEM_C10, g_c1 + n_base);
    CP_COMMIT();
    issue_tile(sb + SMEM_B1, g_tbf + (size_t)(n_base + NT) * DD);
    issue_c1(sb + SMEM_C11, g_c1 + n_base + NT);
    CP_COMMIT();

    int a_row_in_warp = ((lane >> 3) & 1) * 8 + (lane & 7);
    int a_kb16 = ((lane >> 4) & 1) * 16;
    int b_row_in_nb = lane & 7;
    int b_kb16 = (lane >> 3) * 16;

    asm volatile("cp.async.wait_group 1;" ::: "memory");  // A + B0 + c1_0 resident
    __syncthreads();

    // Hoist A fragments (constant across the whole tile loop)
    uint32_t af[4][2][2][4];   // [kq][ms][kk][4]
    #pragma unroll
    for (int kq = 0; kq < 4; kq++) {
        int chunk = kq >> 1;
        int kbyte0 = (kq & 1) * 64;
        uint32_t base = sb + SMEM_A + chunk * 16384;
        #pragma unroll
        for (int ms = 0; ms < 2; ms++) {
            int row = warp_m * 32 + ms * 16 + a_row_in_warp;
            ldsm4(af[kq][ms][0], base + SWZ((uint32_t)(row * 128 + kbyte0 + a_kb16)));
            ldsm4(af[kq][ms][1], base + SWZ((uint32_t)(row * 128 + kbyte0 + 32 + a_kb16)));
        }
    }

    float racc[2][2] = {{0.f, 0.f}, {0.f, 0.f}};

    for (int i = 0; i < TILES; i++) {
        if (i + 1 < TILES) { asm volatile("cp.async.wait_group 1;" ::: "memory"); }
        else               { asm volatile("cp.async.wait_group 0;" ::: "memory"); }
        __syncthreads();

        uint32_t Bb  = sb + ((i & 1) ? SMEM_B1  : SMEM_B0);
        uint32_t c1s = sb + ((i & 1) ? SMEM_C11 : SMEM_C10) + (warp_n * 64 + 2 * tg) * 4;

        // nb pairs: ldsm B for both, 32 MMAs over 4 indep chains, then epilogue.
        #pragma unroll
        for (int np = 0; np < 4; np++) {
            uint32_t bf[2][4][4];   // [nb2][kq][k-sub]
            #pragma unroll
            for (int nb2 = 0; nb2 < 2; nb2++) {
                int row = warp_n * 64 + (np * 2 + nb2) * 8 + b_row_in_nb;
                #pragma unroll
                for (int kq = 0; kq < 4; kq++) {
                    int chunk = kq >> 1;
                    int kbyte0 = (kq & 1) * 64;
                    ldsm4(bf[nb2][kq], Bb + chunk * 16384 +
                          SWZ((uint32_t)(row * 128 + kbyte0 + b_kb16)));
                }
            }
            float acc[2][2][4];     // [nb2][ms][4]
            #pragma unroll
            for (int nb2 = 0; nb2 < 2; nb2++)
                #pragma unroll
                for (int ms = 0; ms < 2; ms++)
                    #pragma unroll
                    for (int c = 0; c < 4; c++) acc[nb2][ms][c] = 0.f;

            // kq -> kk -> nb2 -> ms: same-chain MMAs are 4 issues apart.
            #pragma unroll
            for (int kq = 0; kq < 4; kq++)
                #pragma unroll
                for (int kk = 0; kk < 2; kk++)
                    #pragma unroll
                    for (int nb2 = 0; nb2 < 2; nb2++)
                        #pragma unroll
                        for (int ms = 0; ms < 2; ms++)
                            mma16816(acc[nb2][ms], af[kq][ms][kk], &bf[nb2][kq][kk * 2]);

            // Epilogue for the pair (c1 via LDS, ~29cyc; broadcast across g-lanes)
            #pragma unroll
            for (int nb2 = 0; nb2 < 2; nb2++) {
                float2 w = lds64f(c1s + (np * 2 + nb2) * 32);
                #pragma unroll
                for (int ms = 0; ms < 2; ms++) {
                    racc[ms][0] = fmaf(ex2f(acc[nb2][ms][0]), w.x, racc[ms][0]);
                    racc[ms][0] = fmaf(ex2f(acc[nb2][ms][1]), w.y, racc[ms][0]);
                    racc[ms][1] = fmaf(ex2f(acc[nb2][ms][2]), w.x, racc[ms][1]);
                    racc[ms][1] = fmaf(ex2f(acc[nb2][ms][3]), w.y, racc[ms][1]);
                }
            }
        }

        __syncthreads();   // all warps done reading Bb + c1s
        if (i + 2 < TILES) {
            issue_tile(Bb, g_tbf + (size_t)(n_base + (i + 2) * NT) * DD);
            issue_c1(sb + ((i & 1) ? SMEM_C11 : SMEM_C10), g_c1 + n_base + (i + 2) * NT);
        }
        CP_COMMIT();
    }

    // Reduce over the 4 lanes sharing each row, write deterministic partials.
    #pragma unroll
    for (int ms = 0; ms < 2; ms++)
        #pragma unroll
        for (int h = 0; h < 2; h++) {
            float v = racc[ms][h];
            v += __shfl_xor_sync(0xFFFFFFFFu, v, 1);
            v += __shfl_xor_sync(0xFFFFFFFFu, v, 2);
            if (tg == 0) {
                int b = m0 + warp_m * 32 + ms * 16 + h * 8 + g;
                g_partial[(ns * BB + b) * 2 + warp_n] = v;
            }
        }
}

// ============================================================================
// Final reduction: out[b] = e_x[b] * sum(partials) + bias
// ============================================================================
__global__ void reduce_kernel(const float* __restrict__ bias, float* __restrict__ out) {
    int b = blockIdx.x * blockDim.x + threadIdx.x;
    if (b >= BB) return;
    float s = 0.0f;
    #pragma unroll
    for (int ns = 0; ns < NSPLITS; ns++) {
        s += g_partial[(ns * BB + b) * 2 + 0];
        s += g_partial[(ns * BB + b) * 2 + 1];
    }
    out[b] = fmaf(g_ex[b], s, __ldg(bias));
}

// ============================================================================
// Entry — 4-launch structure
// ============================================================================
extern "C" void kernel_launch(void* const* d_in, const int* in_sizes, int n_in,
                              void* d_out, int out_size) {
    const float* x     = (const float*)d_in[0];   // [2048, 128]
    const float* train = (const float*)d_in[1];   // [32768, 128]
    const float* gamma = (const float*)d_in[2];   // [1]
    const float* W     = (const float*)d_in[3];   // [1, 32768]
    const float* bias  = (const float*)d_in[4];   // [1]
    float* out = (float*)d_out;                   // [2048, 1]

    cudaFuncSetAttribute(rbf_main_kernel,
                         cudaFuncAttributeMaxDynamicSharedMemorySize, SMEM_TOTAL);

    prep_x_kernel<<<(BB * 32) / THREADS, THREADS>>>(x, gamma);
    prep_t_kernel<<<(NN * 32) / THREADS, THREADS>>>(train, gamma, W);
    rbf_main_kernel<<<dim3(NSPLITS, BTILES), THREADS, SMEM_TOTAL>>>();
    reduce_kernel<<<BB / THREADS, THREADS>>>(bias, out);
}